// round 5
// baseline (speedup 1.0000x reference)
#include <cuda_runtime.h>
#include <math.h>

#define NN 100000
#define EE 1600000
#define HEADS 4
#define HID 16
#define F1 64
#define NC 16
#define NEG 0.2f

// ---------------- scratch (device globals) ----------------
__device__ __align__(128) float g_h1[NN * F1];
__device__ __align__(128) float g_as1[NN * HEADS];
__device__ __align__(128) float g_ad1[NN * HEADS];
__device__ __align__(128) float g_hw2[NN * NC];
__device__ __align__(128) float g_as2[NN];
__device__ __align__(128) float g_ad2[NN];
__device__ __align__(128) int   g_cnt[NN];
__device__ __align__(128) int   g_offs[NN + 1];
__device__ __align__(128) int   g_cur[NN];
__device__ __align__(128) int   g_srcs[EE];

__device__ __forceinline__ float lrelu(float v) { return v >= 0.f ? v : NEG * v; }

// f32x2 packed helpers
__device__ __forceinline__ unsigned long long pk2(float lo, float hi) {
    unsigned long long r;
    asm("mov.b64 %0, {%1, %2};" : "=l"(r) : "f"(lo), "f"(hi));
    return r;
}
__device__ __forceinline__ void fma2(unsigned long long& d, unsigned long long a, unsigned long long b) {
    asm("fma.rn.f32x2 %0, %1, %2, %0;" : "+l"(d) : "l"(a), "l"(b));
}
__device__ __forceinline__ float2 upk2(unsigned long long v) {
    float2 f;
    asm("mov.b64 {%0, %1}, %2;" : "=f"(f.x), "=f"(f.y) : "l"(v));
    return f;
}

// ---------------- CSR build ----------------
__global__ void zero_kernel(int n) {
    int t = blockIdx.x * blockDim.x + threadIdx.x;
    if (t < n) g_cnt[t] = 0;
}

__global__ void hist_kernel(const int* __restrict__ ei, int E) {
    int t = blockIdx.x * blockDim.x + threadIdx.x;
    int e = t * 4;
    if (e + 4 <= E) {
        int4 d = *(const int4*)(ei + (size_t)E + e);
        atomicAdd(&g_cnt[d.x], 1);
        atomicAdd(&g_cnt[d.y], 1);
        atomicAdd(&g_cnt[d.z], 1);
        atomicAdd(&g_cnt[d.w], 1);
    } else {
        for (int i = e; i < E; i++) atomicAdd(&g_cnt[ei[(size_t)E + i]], 1);
    }
}

__global__ void scan_kernel(int n) {
    __shared__ int sums[1024];
    int t = threadIdx.x;
    int per = (n + 1023) >> 10;
    int st = t * per, en = min(st + per, n);
    int s = 0;
    for (int i = st; i < en; i++) s += g_cnt[i];
    sums[t] = s;
    __syncthreads();
    for (int off = 1; off < 1024; off <<= 1) {
        int v = (t >= off) ? sums[t - off] : 0;
        __syncthreads();
        sums[t] += v;
        __syncthreads();
    }
    int run = (t == 0) ? 0 : sums[t - 1];
    for (int i = st; i < en; i++) {
        int c = g_cnt[i];
        g_offs[i] = run;
        g_cur[i] = run;
        run += c;
    }
    if (t == 1023) g_offs[n] = run;
}

__global__ void scatter_kernel(const int* __restrict__ ei, int E) {
    int t = blockIdx.x * blockDim.x + threadIdx.x;
    int e = t * 4;
    if (e + 4 <= E) {
        int4 s = *(const int4*)(ei + e);
        int4 d = *(const int4*)(ei + (size_t)E + e);
        g_srcs[atomicAdd(&g_cur[d.x], 1)] = s.x;
        g_srcs[atomicAdd(&g_cur[d.y], 1)] = s.y;
        g_srcs[atomicAdd(&g_cur[d.z], 1)] = s.z;
        g_srcs[atomicAdd(&g_cur[d.w], 1)] = s.w;
    } else {
        for (int i = e; i < E; i++) {
            int src = ei[i], dst = ei[(size_t)E + i];
            g_srcs[atomicAdd(&g_cur[dst], 1)] = src;
        }
    }
}

// ---------------- layer 1 GEMM: h1 = x @ W1, f32x2 FMA, attn epilogue ----------------
// block: 256 threads, 128 rows; per thread 4 rows x 8 cols (4 f32x2 col-pairs)
#define BM1 128
#define AS_LD 132   // padded row stride (floats) to dodge LDS bank conflicts
__global__ void gemm1_kernel(const float* __restrict__ x, const float* __restrict__ W1,
                             const float* __restrict__ att_src, const float* __restrict__ att_dst,
                             int n) {
    extern __shared__ float sm[];
    float* As = sm;                      // 128 x 132
    float* Bs = sm + BM1 * AS_LD;        // 128 x 64
    int tid = threadIdx.x;
    int row0 = blockIdx.x * BM1;

    for (int i = tid; i < BM1 * 32; i += 256) {
        int r = i >> 5, c4 = (i & 31) << 2;
        int gr = row0 + r;
        float4 v = make_float4(0.f, 0.f, 0.f, 0.f);
        if (gr < n) v = *(const float4*)(x + (size_t)gr * 128 + c4);
        *(float4*)(As + r * AS_LD + c4) = v;
    }
    for (int i = tid; i < 128 * 16; i += 256) {
        int r = i >> 4, c4 = (i & 15) << 2;
        *(float4*)(Bs + r * 64 + c4) = *(const float4*)(W1 + r * 64 + c4);
    }
    __syncthreads();

    int tx = tid & 7, ty = tid >> 3;     // 8 col-groups x 32 row-groups
    int r0 = ty * 4;

    unsigned long long acc[4][4];
#pragma unroll
    for (int i = 0; i < 4; i++)
#pragma unroll
        for (int j = 0; j < 4; j++) acc[i][j] = 0ull;

#pragma unroll 2
    for (int k4 = 0; k4 < 128; k4 += 4) {
        float4 a4[4];
#pragma unroll
        for (int i = 0; i < 4; i++) a4[i] = *(float4*)(As + (r0 + i) * AS_LD + k4);
#pragma unroll
        for (int kk = 0; kk < 4; kk++) {
            const float* brow = Bs + (size_t)(k4 + kk) * 64 + tx * 8;
            float4 b0 = *(const float4*)(brow);
            float4 b1 = *(const float4*)(brow + 4);
            unsigned long long bp[4];
            bp[0] = pk2(b0.x, b0.y);
            bp[1] = pk2(b0.z, b0.w);
            bp[2] = pk2(b1.x, b1.y);
            bp[3] = pk2(b1.z, b1.w);
#pragma unroll
            for (int i = 0; i < 4; i++) {
                float av = (kk == 0) ? a4[i].x : (kk == 1) ? a4[i].y : (kk == 2) ? a4[i].z : a4[i].w;
                unsigned long long ap = pk2(av, av);
                fma2(acc[i][0], ap, bp[0]);
                fma2(acc[i][1], ap, bp[1]);
                fma2(acc[i][2], ap, bp[2]);
                fma2(acc[i][3], ap, bp[3]);
            }
        }
    }

    int head = tx >> 1;
#pragma unroll
    for (int i = 0; i < 4; i++) {
        int gr = row0 + r0 + i;
        float c[8];
#pragma unroll
        for (int j = 0; j < 4; j++) {
            float2 f = upk2(acc[i][j]);
            c[2 * j] = f.x;
            c[2 * j + 1] = f.y;
        }
        if (gr < n) {
            float* hp = g_h1 + (size_t)gr * 64 + tx * 8;
            *(float4*)(hp)     = make_float4(c[0], c[1], c[2], c[3]);
            *(float4*)(hp + 4) = make_float4(c[4], c[5], c[6], c[7]);
        }
        float ps = 0.f, pd = 0.f;
#pragma unroll
        for (int j = 0; j < 8; j++) {
            ps += c[j] * att_src[tx * 8 + j];
            pd += c[j] * att_dst[tx * 8 + j];
        }
        ps += __shfl_xor_sync(0xffffffffu, ps, 1);
        pd += __shfl_xor_sync(0xffffffffu, pd, 1);
        if (!(tx & 1) && gr < n) {
            g_as1[(size_t)gr * 4 + head] = ps;
            g_ad1[(size_t)gr * 4 + head] = pd;
        }
    }
}

// ---------------- layer 1 aggregation: warp per dst node ----------------
__global__ void agg1_kernel(const float* __restrict__ b1, float* __restrict__ emb, int n) {
    int w = (blockIdx.x * blockDim.x + threadIdx.x) >> 5;
    if (w >= n) return;
    int lane = threadIdx.x & 31;
    int u = w;
    int h0 = lane >> 4;

    float4 ad4 = *(const float4*)(g_ad1 + (size_t)u * 4);
    float4 asu = *(const float4*)(g_as1 + (size_t)u * 4);

    float exs0 = expf(lrelu(((h0 == 0) ? asu.x : asu.y) + ((h0 == 0) ? ad4.x : ad4.y)));
    float exs1 = expf(lrelu(((h0 == 0) ? asu.z : asu.w) + ((h0 == 0) ? ad4.z : ad4.w)));
    float acc0 = exs0 * g_h1[(size_t)u * 64 + lane];
    float acc1 = exs1 * g_h1[(size_t)u * 64 + 32 + lane];
    float den0 = exs0, den1 = exs1;

    int beg = g_offs[u], end = g_offs[u + 1];
    for (int base = beg; base < end; base += 32) {
        int idx = base + lane;
        int src = (idx < end) ? g_srcs[idx] : 0;
        float4 asv = *(const float4*)(g_as1 + (size_t)src * 4);
        float ex_x = expf(lrelu(asv.x + ad4.x));
        float ex_y = expf(lrelu(asv.y + ad4.y));
        float ex_z = expf(lrelu(asv.z + ad4.z));
        float ex_w = expf(lrelu(asv.w + ad4.w));
        int cnt = min(end - base, 32);
#pragma unroll 4
        for (int k = 0; k < cnt; k++) {
            int   sk  = __shfl_sync(0xffffffffu, src, k);
            float e0a = __shfl_sync(0xffffffffu, ex_x, k);
            float e0b = __shfl_sync(0xffffffffu, ex_y, k);
            float e1a = __shfl_sync(0xffffffffu, ex_z, k);
            float e1b = __shfl_sync(0xffffffffu, ex_w, k);
            float w0 = h0 ? e0b : e0a;
            float w1 = h0 ? e1b : e1a;
            float x0 = g_h1[(size_t)sk * 64 + lane];
            float x1 = g_h1[(size_t)sk * 64 + 32 + lane];
            acc0 = fmaf(w0, x0, acc0);
            acc1 = fmaf(w1, x1, acc1);
            den0 += w0;
            den1 += w1;
        }
    }
    float o0 = acc0 / fmaxf(den0, 1e-16f) + b1[lane];
    float o1 = acc1 / fmaxf(den1, 1e-16f) + b1[lane + 32];
    o0 = o0 > 0.f ? o0 : expm1f(o0);
    o1 = o1 > 0.f ? o1 : expm1f(o1);
    emb[(size_t)u * 64 + lane] = o0;
    emb[(size_t)u * 64 + 32 + lane] = o1;
}

// ---------------- layer 2 GEMM (N x 64 @ 64 x 16) + attn coef epilogue ----------------
__global__ void gemm2_kernel(const float* __restrict__ emb, const float* __restrict__ W2,
                             const float* __restrict__ att_src, const float* __restrict__ att_dst,
                             int n) {
    __shared__ float Es[16 * 64];
    __shared__ float Ws[64 * 16];
    int tid = threadIdx.x;
    int n0 = blockIdx.x * 16;
    for (int i = tid; i < 64 * 16; i += 256) Ws[i] = W2[i];
    for (int i = tid; i < 16 * 64; i += 256) {
        int r = i >> 6, c = i & 63;
        int gn = n0 + r;
        Es[i] = (gn < n) ? emb[(size_t)gn * 64 + c] : 0.f;
    }
    __syncthreads();
    int ni = tid >> 4, j = tid & 15;
    int gn = n0 + ni;
    float s = 0.f;
#pragma unroll
    for (int c = 0; c < 64; c++) s += Es[ni * 64 + c] * Ws[c * 16 + j];
    if (gn < n) g_hw2[(size_t)gn * 16 + j] = s;

    float ps = s * att_src[j], pd = s * att_dst[j];
#pragma unroll
    for (int o = 8; o; o >>= 1) {
        ps += __shfl_xor_sync(0xffffffffu, ps, o);
        pd += __shfl_xor_sync(0xffffffffu, pd, o);
    }
    if (j == 0 && gn < n) {
        g_as2[gn] = ps;
        g_ad2[gn] = pd;
    }
}

// ---------------- layer 2 aggregation + log_softmax: warp per dst node ----------------
__global__ void agg2_kernel(const float* __restrict__ b2, float* __restrict__ out, int n) {
    int w = (blockIdx.x * blockDim.x + threadIdx.x) >> 5;
    if (w >= n) return;
    int lane = threadIdx.x & 31;
    int u = w;
    int c = lane & 15;
    int half = lane >> 4;

    float ad = g_ad2[u];
    float exs = expf(lrelu(g_as2[u] + ad));
    float acc = 0.f, den = 0.f;
    if (half == 0) {
        acc = exs * g_hw2[(size_t)u * 16 + c];
        den = exs;
    }

    int beg = g_offs[u], end = g_offs[u + 1];
    for (int base = beg; base < end; base += 32) {
        int idx = base + lane;
        int src = (idx < end) ? g_srcs[idx] : 0;
        float ex = (idx < end) ? expf(lrelu(g_as2[src] + ad)) : 0.f;
        int cnt = min(end - base, 32);
#pragma unroll 4
        for (int k = 0; k < cnt; k += 2) {
            int kk = k + half;
            int   sk = __shfl_sync(0xffffffffu, src, kk & 31);
            float wv = __shfl_sync(0xffffffffu, ex, kk & 31);
            if (kk < cnt) {
                float x = g_hw2[(size_t)sk * 16 + c];
                acc = fmaf(wv, x, acc);
                den += wv;
            }
        }
    }
    acc += __shfl_xor_sync(0xffffffffu, acc, 16);
    den += __shfl_xor_sync(0xffffffffu, den, 16);

    float logit = acc / fmaxf(den, 1e-16f) + b2[c];
    float mx = logit;
#pragma unroll
    for (int o = 8; o; o >>= 1) mx = fmaxf(mx, __shfl_xor_sync(0xffffffffu, mx, o));
    float se = expf(logit - mx);
#pragma unroll
    for (int o = 8; o; o >>= 1) se += __shfl_xor_sync(0xffffffffu, se, o);
    float res = logit - (mx + logf(se));
    if (half == 0) out[(size_t)u * 16 + c] = res;
}

// ---------------- launch ----------------
extern "C" void kernel_launch(void* const* d_in, const int* in_sizes, int n_in,
                              void* d_out, int out_size) {
    const float* x        = (const float*)d_in[0];
    const int*   ei       = (const int*)d_in[1];
    const float* W1       = (const float*)d_in[2];
    const float* att_src1 = (const float*)d_in[3];
    const float* att_dst1 = (const float*)d_in[4];
    const float* b1       = (const float*)d_in[5];
    const float* W2       = (const float*)d_in[6];
    const float* att_src2 = (const float*)d_in[7];
    const float* att_dst2 = (const float*)d_in[8];
    const float* b2       = (const float*)d_in[9];

    int n = in_sizes[0] / 128;      // 100000
    int E = in_sizes[1] / 2;        // 1600000

    float* out_ls = (float*)d_out;
    float* emb    = (float*)d_out + (size_t)n * NC;

    int gemm1_smem = (BM1 * AS_LD + 128 * 64) * 4;
    cudaFuncSetAttribute(gemm1_kernel, cudaFuncAttributeMaxDynamicSharedMemorySize, gemm1_smem);

    int e4b = ((E + 3) / 4 + 255) / 256;
    int nb = (n + 255) / 256;
    int wb = (n * 32 + 255) / 256;

    // CSR build (shared by both layers)
    zero_kernel<<<nb, 256>>>(n);
    hist_kernel<<<e4b, 256>>>(ei, E);
    scan_kernel<<<1, 1024>>>(n);
    scatter_kernel<<<e4b, 256>>>(ei, E);

    // layer 1
    gemm1_kernel<<<(n + BM1 - 1) / BM1, 256, gemm1_smem>>>(x, W1, att_src1, att_dst1, n);
    agg1_kernel<<<wb, 256>>>(b1, emb, n);

    // layer 2
    gemm2_kernel<<<(n + 15) / 16, 256>>>(emb, W2, att_src2, att_dst2, n);
    agg2_kernel<<<wb, 256>>>(b2, out_ls, n);
}

// round 6
// speedup vs baseline: 1.8464x; 1.8464x over previous
#include <cuda_runtime.h>
#include <math.h>

#define NN 100000
#define EE 1600000
#define HEADS 4
#define HID 16
#define F1 64
#define NC 16
#define NEG 0.2f
#define NB_SCAN 512

// ---------------- scratch (device globals) ----------------
__device__ __align__(128) float g_h1[NN * F1];
__device__ __align__(128) float g_as1[NN * HEADS];
__device__ __align__(128) float g_ad1[NN * HEADS];
__device__ __align__(128) float g_hw2[NN * NC];
__device__ __align__(128) float g_as2[NN];
__device__ __align__(128) float g_ad2[NN];
__device__ __align__(128) int   g_cnt[NN];
__device__ __align__(128) int   g_offs[NN + 1];
__device__ __align__(128) int   g_cur[NN];
__device__ __align__(128) int   g_srcs[EE];
__device__ __align__(128) int   g_bsum[NB_SCAN];
__device__ __align__(128) int   g_bincl[NB_SCAN];

__device__ __forceinline__ float lrelu(float v) { return v >= 0.f ? v : NEG * v; }

// ---------------- CSR build ----------------
__global__ void zero_kernel(int n) {
    int t = blockIdx.x * blockDim.x + threadIdx.x;
    if (t < n) g_cnt[t] = 0;
}

__global__ void hist_kernel(const int* __restrict__ ei, int E) {
    int e = blockIdx.x * blockDim.x + threadIdx.x;
    if (e >= E) return;
    atomicAdd(&g_cnt[ei[(size_t)E + e]], 1);
}

// phase A: per-block partial sums over chunks of the count array
__global__ void scanA_kernel(int n) {
    __shared__ int red[256];
    int b = blockIdx.x, t = threadIdx.x;
    int ch = (n + NB_SCAN - 1) / NB_SCAN;
    int base = b * ch;
    int s = 0;
    for (int i = t; i < ch; i += 256) {
        int idx = base + i;
        if (idx < n) s += g_cnt[idx];
    }
    red[t] = s;
    __syncthreads();
    for (int o = 128; o; o >>= 1) {
        if (t < o) red[t] += red[t + o];
        __syncthreads();
    }
    if (t == 0) g_bsum[b] = red[0];
}

// phase B: inclusive scan of the 512 block sums (single block)
__global__ void scanB_kernel(int n) {
    __shared__ int sm[NB_SCAN];
    int t = threadIdx.x;
    sm[t] = g_bsum[t];
    __syncthreads();
    for (int o = 1; o < NB_SCAN; o <<= 1) {
        int v = (t >= o) ? sm[t - o] : 0;
        __syncthreads();
        sm[t] += v;
        __syncthreads();
    }
    g_bincl[t] = sm[t];
    if (t == NB_SCAN - 1) g_offs[n] = sm[t];
}

// phase C: per-block local exclusive scan + global base -> offs/cur
__global__ void scanC_kernel(int n) {
    __shared__ int sm[512];
    int b = blockIdx.x, t = threadIdx.x;
    int ch = (n + NB_SCAN - 1) / NB_SCAN;          // <= 512 assumed
    int base = b * ch;
    int gbase = g_bincl[b] - g_bsum[b];            // exclusive block prefix
    for (int i = t; i < 512; i += 256) {
        int idx = base + i;
        sm[i] = (i < ch && idx < n) ? g_cnt[idx] : 0;
    }
    __syncthreads();
    for (int o = 1; o < 512; o <<= 1) {
        int v0 = (t >= o) ? sm[t - o] : 0;
        int v1 = (t + 256 >= o) ? sm[t + 256 - o] : 0;
        __syncthreads();
        sm[t] += v0;
        sm[t + 256] += v1;
        __syncthreads();
    }
    for (int i = t; i < ch; i += 256) {
        int idx = base + i;
        if (idx < n) {
            int excl = gbase + (i ? sm[i - 1] : 0);
            g_offs[idx] = excl;
            g_cur[idx] = excl;
        }
    }
}

__global__ void scatter_kernel(const int* __restrict__ ei, int E) {
    int e = blockIdx.x * blockDim.x + threadIdx.x;
    if (e >= E) return;
    int src = ei[e], dst = ei[(size_t)E + e];
    int pos = atomicAdd(&g_cur[dst], 1);
    g_srcs[pos] = src;
}

// ---------------- layer 1 GEMM: h1 = x @ W1 + attn coef epilogue ----------------
__global__ void gemm1_kernel(const float* __restrict__ x, const float* __restrict__ W1,
                             const float* __restrict__ att_src, const float* __restrict__ att_dst,
                             int n) {
    extern __shared__ float sm[];
    float* As = sm;               // 64 x 128
    float* Bs = sm + 64 * 128;    // 128 x 64
    int tid = threadIdx.x;
    int row0 = blockIdx.x * 64;

    for (int i = tid; i < 64 * 32; i += 256) {
        int r = i >> 5, c4 = (i & 31) << 2;
        float4 v = make_float4(0.f, 0.f, 0.f, 0.f);
        int gr = row0 + r;
        if (gr < n) v = *(const float4*)(x + (size_t)gr * 128 + c4);
        *(float4*)(As + r * 128 + c4) = v;
    }
    for (int i = tid; i < 128 * 16; i += 256) {
        int r = i >> 4, c4 = (i & 15) << 2;
        *(float4*)(Bs + r * 64 + c4) = *(const float4*)(W1 + r * 64 + c4);
    }
    __syncthreads();

    int tx = tid & 15, ty = tid >> 4;
    float acc[4][4];
#pragma unroll
    for (int i = 0; i < 4; i++)
#pragma unroll
        for (int j = 0; j < 4; j++) acc[i][j] = 0.f;

#pragma unroll
    for (int k4 = 0; k4 < 128; k4 += 4) {
        float4 a[4], b[4];
#pragma unroll
        for (int i = 0; i < 4; i++) a[i] = *(float4*)(As + (ty * 4 + i) * 128 + k4);
#pragma unroll
        for (int kk = 0; kk < 4; kk++) b[kk] = *(float4*)(Bs + (size_t)(k4 + kk) * 64 + tx * 4);
#pragma unroll
        for (int kk = 0; kk < 4; kk++) {
            float4 bv = b[kk];
#pragma unroll
            for (int i = 0; i < 4; i++) {
                float av = (kk == 0) ? a[i].x : (kk == 1) ? a[i].y : (kk == 2) ? a[i].z : a[i].w;
                acc[i][0] += av * bv.x;
                acc[i][1] += av * bv.y;
                acc[i][2] += av * bv.z;
                acc[i][3] += av * bv.w;
            }
        }
    }

    int head = tx >> 2;
    int coff = head * 16 + (tx & 3) * 4;
#pragma unroll
    for (int i = 0; i < 4; i++) {
        int gr = row0 + ty * 4 + i;
        if (gr < n) {
            *(float4*)(g_h1 + (size_t)gr * 64 + tx * 4) =
                make_float4(acc[i][0], acc[i][1], acc[i][2], acc[i][3]);
        }
        float ps = 0.f, pd = 0.f;
#pragma unroll
        for (int j = 0; j < 4; j++) {
            ps += acc[i][j] * att_src[coff + j];
            pd += acc[i][j] * att_dst[coff + j];
        }
        ps += __shfl_xor_sync(0xffffffffu, ps, 1);
        pd += __shfl_xor_sync(0xffffffffu, pd, 1);
        ps += __shfl_xor_sync(0xffffffffu, ps, 2);
        pd += __shfl_xor_sync(0xffffffffu, pd, 2);
        if ((tx & 3) == 0 && gr < n) {
            g_as1[(size_t)gr * 4 + head] = ps;
            g_ad1[(size_t)gr * 4 + head] = pd;
        }
    }
}

// ---------------- layer 1 aggregation: warp per dst, 4 edge-groups x 8 lanes ----------------
// lane = g*8 + l8; lane owns channels [l8*8, l8*8+8) (single head = l8>>1)
__global__ void agg1_kernel(const float* __restrict__ b1, float* __restrict__ emb, int n) {
    int w = (blockIdx.x * blockDim.x + threadIdx.x) >> 5;
    if (w >= n) return;
    int lane = threadIdx.x & 31;
    int g = lane >> 3, l8 = lane & 7;
    int c0 = l8 * 8;
    int head = l8 >> 1;
    int u = w;

    float adh = g_ad1[(size_t)u * 4 + head];
    float acc[8];
#pragma unroll
    for (int i = 0; i < 8; i++) acc[i] = 0.f;
    float den = 0.f;

    if (g == 0) {   // self-loop handled by group 0
        float exs = expf(lrelu(g_as1[(size_t)u * 4 + head] + adh));
        const float* hp = g_h1 + (size_t)u * 64 + c0;
        float4 v0 = *(const float4*)(hp);
        float4 v1 = *(const float4*)(hp + 4);
        acc[0] = exs * v0.x; acc[1] = exs * v0.y; acc[2] = exs * v0.z; acc[3] = exs * v0.w;
        acc[4] = exs * v1.x; acc[5] = exs * v1.y; acc[6] = exs * v1.z; acc[7] = exs * v1.w;
        den = exs;
    }

    int beg = g_offs[u], end = g_offs[u + 1];
    for (int idx = beg + g; idx < end; idx += 4) {
        int src = g_srcs[idx];
        float ex = expf(lrelu(g_as1[(size_t)src * 4 + head] + adh));
        const float* hp = g_h1 + (size_t)src * 64 + c0;
        float4 v0 = *(const float4*)(hp);
        float4 v1 = *(const float4*)(hp + 4);
        acc[0] = fmaf(ex, v0.x, acc[0]);
        acc[1] = fmaf(ex, v0.y, acc[1]);
        acc[2] = fmaf(ex, v0.z, acc[2]);
        acc[3] = fmaf(ex, v0.w, acc[3]);
        acc[4] = fmaf(ex, v1.x, acc[4]);
        acc[5] = fmaf(ex, v1.y, acc[5]);
        acc[6] = fmaf(ex, v1.z, acc[6]);
        acc[7] = fmaf(ex, v1.w, acc[7]);
        den += ex;
    }

    // reduce across the 4 groups (lane bits 3,4)
#pragma unroll
    for (int o = 8; o <= 16; o <<= 1) {
        den += __shfl_xor_sync(0xffffffffu, den, o);
#pragma unroll
        for (int i = 0; i < 8; i++) acc[i] += __shfl_xor_sync(0xffffffffu, acc[i], o);
    }

    if (g == 0) {
        float inv = 1.f / fmaxf(den, 1e-16f);
        float o[8];
#pragma unroll
        for (int i = 0; i < 8; i++) {
            float v = acc[i] * inv + b1[c0 + i];
            o[i] = v > 0.f ? v : expm1f(v);
        }
        float* ep = emb + (size_t)u * 64 + c0;
        *(float4*)(ep)     = make_float4(o[0], o[1], o[2], o[3]);
        *(float4*)(ep + 4) = make_float4(o[4], o[5], o[6], o[7]);
    }
}

// ---------------- layer 2 GEMM (N x 64 @ 64 x 16) + attn coef epilogue ----------------
__global__ void gemm2_kernel(const float* __restrict__ emb, const float* __restrict__ W2,
                             const float* __restrict__ att_src, const float* __restrict__ att_dst,
                             int n) {
    __shared__ float Es[16 * 64];
    __shared__ float Ws[64 * 16];
    int tid = threadIdx.x;
    int n0 = blockIdx.x * 16;
    for (int i = tid; i < 64 * 16; i += 256) Ws[i] = W2[i];
    for (int i = tid; i < 16 * 64; i += 256) {
        int r = i >> 6, c = i & 63;
        int gn = n0 + r;
        Es[i] = (gn < n) ? emb[(size_t)gn * 64 + c] : 0.f;
    }
    __syncthreads();
    int ni = tid >> 4, j = tid & 15;
    int gn = n0 + ni;
    float s = 0.f;
#pragma unroll
    for (int c = 0; c < 64; c++) s += Es[ni * 64 + c] * Ws[c * 16 + j];
    if (gn < n) g_hw2[(size_t)gn * 16 + j] = s;

    float ps = s * att_src[j], pd = s * att_dst[j];
#pragma unroll
    for (int o = 8; o; o >>= 1) {
        ps += __shfl_xor_sync(0xffffffffu, ps, o);
        pd += __shfl_xor_sync(0xffffffffu, pd, o);
    }
    if (j == 0 && gn < n) {
        g_as2[gn] = ps;
        g_ad2[gn] = pd;
    }
}

// ---------------- layer 2 aggregation: warp per dst, 8 edge-groups x 4 lanes ----------------
__global__ void agg2_kernel(const float* __restrict__ b2, float* __restrict__ out, int n) {
    int w = (blockIdx.x * blockDim.x + threadIdx.x) >> 5;
    if (w >= n) return;
    int lane = threadIdx.x & 31;
    int g = lane >> 2, l4 = lane & 3;
    int c0 = l4 * 4;
    int u = w;

    float ad = g_ad2[u];
    float acc0 = 0.f, acc1 = 0.f, acc2 = 0.f, acc3 = 0.f, den = 0.f;

    if (g == 0) {
        float exs = expf(lrelu(g_as2[u] + ad));
        float4 v = *(const float4*)(g_hw2 + (size_t)u * 16 + c0);
        acc0 = exs * v.x; acc1 = exs * v.y; acc2 = exs * v.z; acc3 = exs * v.w;
        den = exs;
    }

    int beg = g_offs[u], end = g_offs[u + 1];
    for (int idx = beg + g; idx < end; idx += 8) {
        int src = g_srcs[idx];
        float ex = expf(lrelu(g_as2[src] + ad));
        float4 v = *(const float4*)(g_hw2 + (size_t)src * 16 + c0);
        acc0 = fmaf(ex, v.x, acc0);
        acc1 = fmaf(ex, v.y, acc1);
        acc2 = fmaf(ex, v.z, acc2);
        acc3 = fmaf(ex, v.w, acc3);
        den += ex;
    }

    // reduce across the 8 groups (lane bits 2,3,4)
#pragma unroll
    for (int o = 4; o <= 16; o <<= 1) {
        den  += __shfl_xor_sync(0xffffffffu, den, o);
        acc0 += __shfl_xor_sync(0xffffffffu, acc0, o);
        acc1 += __shfl_xor_sync(0xffffffffu, acc1, o);
        acc2 += __shfl_xor_sync(0xffffffffu, acc2, o);
        acc3 += __shfl_xor_sync(0xffffffffu, acc3, o);
    }

    // every lane now holds the same (per-l4) values; compute log_softmax warp-wide
    float inv = 1.f / fmaxf(den, 1e-16f);
    float l0 = acc0 * inv + b2[c0];
    float l1 = acc1 * inv + b2[c0 + 1];
    float l2 = acc2 * inv + b2[c0 + 2];
    float l3 = acc3 * inv + b2[c0 + 3];
    float mx = fmaxf(fmaxf(l0, l1), fmaxf(l2, l3));
#pragma unroll
    for (int o = 1; o <= 2; o <<= 1) mx = fmaxf(mx, __shfl_xor_sync(0xffffffffu, mx, o));
    float se = expf(l0 - mx) + expf(l1 - mx) + expf(l2 - mx) + expf(l3 - mx);
#pragma unroll
    for (int o = 1; o <= 2; o <<= 1) se += __shfl_xor_sync(0xffffffffu, se, o);
    float lse = mx + logf(se);
    if (g == 0) {
        *(float4*)(out + (size_t)u * 16 + c0) =
            make_float4(l0 - lse, l1 - lse, l2 - lse, l3 - lse);
    }
}

// ---------------- launch ----------------
extern "C" void kernel_launch(void* const* d_in, const int* in_sizes, int n_in,
                              void* d_out, int out_size) {
    const float* x        = (const float*)d_in[0];
    const int*   ei       = (const int*)d_in[1];
    const float* W1       = (const float*)d_in[2];
    const float* att_src1 = (const float*)d_in[3];
    const float* att_dst1 = (const float*)d_in[4];
    const float* b1       = (const float*)d_in[5];
    const float* W2       = (const float*)d_in[6];
    const float* att_src2 = (const float*)d_in[7];
    const float* att_dst2 = (const float*)d_in[8];
    const float* b2       = (const float*)d_in[9];

    int n = in_sizes[0] / 128;      // 100000
    int E = in_sizes[1] / 2;        // 1600000

    float* out_ls = (float*)d_out;
    float* emb    = (float*)d_out + (size_t)n * NC;

    cudaFuncSetAttribute(gemm1_kernel, cudaFuncAttributeMaxDynamicSharedMemorySize, 64 * 1024);

    int eb = (E + 255) / 256;
    int nb = (n + 255) / 256;
    int wb = (n * 32 + 255) / 256;

    // CSR build (shared by both layers)
    zero_kernel<<<nb, 256>>>(n);
    hist_kernel<<<eb, 256>>>(ei, E);
    scanA_kernel<<<NB_SCAN, 256>>>(n);
    scanB_kernel<<<1, NB_SCAN>>>(n);
    scanC_kernel<<<NB_SCAN, 256>>>(n);
    scatter_kernel<<<eb, 256>>>(ei, E);

    // layer 1
    gemm1_kernel<<<(n + 63) / 64, 256, 64 * 1024>>>(x, W1, att_src1, att_dst1, n);
    agg1_kernel<<<wb, 256>>>(b1, emb, n);

    // layer 2
    gemm2_kernel<<<(n + 15) / 16, 256>>>(emb, W2, att_src2, att_dst2, n);
    agg2_kernel<<<wb, 256>>>(b2, out_ls, n);
}